// round 4
// baseline (speedup 1.0000x reference)
#include <cuda_runtime.h>
#include <cstdint>

#define CRF_B 1024
#define CRF_S 512
#define CRF_T 64

// Device scratch (static globals: allowed, no allocation)
__device__ float g_partial[CRF_B];
__device__ unsigned int g_count = 0;

__device__ __forceinline__ float ex2f(float x) {
    float y; asm("ex2.approx.ftz.f32 %0, %1;" : "=f"(y) : "f"(x)); return y;
}
__device__ __forceinline__ float lg2f(float x) {
    float y; asm("lg2.approx.f32 %0, %1;" : "=f"(y) : "f"(x)); return y;
}
__device__ __forceinline__ unsigned long long fma2(unsigned long long a,
                                                   unsigned long long b,
                                                   unsigned long long c) {
    unsigned long long d;
    asm("fma.rn.f32x2 %0, %1, %2, %3;" : "=l"(d) : "l"(a), "l"(b), "l"(c));
    return d;
}
__device__ __forceinline__ unsigned long long pack2(float lo, float hi) {
    unsigned long long d;
    asm("mov.b64 %0, {%1, %2};" : "=l"(d) : "f"(lo), "f"(hi));
    return d;
}
__device__ __forceinline__ void unpack2(float& lo, float& hi, unsigned long long v) {
    asm("mov.b64 {%0, %1}, %2;" : "=f"(lo), "=f"(hi) : "l"(v));
}

// One CTA (64 threads) per batch element. Thread j owns state/column j.
// Scaled forward algorithm in the linear domain:
//   p_stored^{(t)}_j = exp(alpha^{(t)}_j) * 2^{-C_t},  C_{t+1} = C_t + lg2(p_stored_0)
// so the recurrence is pure FMA + 1 ex2 + 1 lg2 per step, one barrier per step.
__global__ void __launch_bounds__(CRF_T) crf_scan_kernel(
    const float* __restrict__ inputs,        // [B, S, T]
    const float* __restrict__ trans,         // [T, T]
    const unsigned char* __restrict__ masks, // [B, S]
    const int* __restrict__ tags,            // [B, S]
    float* __restrict__ out, int out_size)
{
    const int b = blockIdx.x;
    const int j = threadIdx.x;
    const float L = 1.4426950408889634f;  // log2(e)

    __shared__ __align__(16) float p_sh[2][CRF_T];
    __shared__ float red[CRF_T];
    __shared__ int tag_sh[CRF_S];
    __shared__ unsigned char mask_sh[CRF_S];
    __shared__ bool is_last;

    const float* xb = inputs + (size_t)b * CRF_S * CRF_T;
    const int* tg = tags + (size_t)b * CRF_S;
    const unsigned char* mk = masks + (size_t)b * CRF_S;

    // Stage tags + masks
    for (int s = j; s < CRF_S; s += CRF_T) {
        tag_sh[s] = tg[s];
        mask_sh[s] = mk[s];
    }
    __syncthreads();

    // unary + binary partial sums (strided over s)
    float ub = 0.f;
    for (int s = j; s < CRF_S; s += CRF_T) {
        if (!mask_sh[s]) {
            ub += xb[s * CRF_T + tag_sh[s]];
            if (s >= 1) ub += trans[tag_sh[s - 1] * CRF_T + tag_sh[s]];
        }
    }

    // E2[k] = packed { exp(trans[2k][j]), exp(trans[2k+1][j]) } in base-2 form
    unsigned long long E2[CRF_T / 2];
#pragma unroll
    for (int k = 0; k < CRF_T / 2; k++) {
        float e0 = ex2f(L * trans[(2 * k) * CRF_T + j]);
        float e1 = ex2f(L * trans[(2 * k + 1) * CRF_T + j]);
        E2[k] = pack2(e0, e1);
    }

    // Init: alpha_0 = x[0,:], scale anchor A = L*x[0,0]
    float A = L * xb[0];                   // broadcast load
    float pj = ex2f(fmaf(L, xb[j], -A));   // p_stored = 2^(L*a0_j - A)
    float Kacc = A;                        // C_1 = A
    p_sh[0][j] = pj;
    __syncthreads();

    float xnext = xb[CRF_T + j];           // prefetch x for t=1

#pragma unroll 1
    for (int t = 1; t < CRF_S; t++) {
        const int pb = (t - 1) & 1;
        float p0 = p_sh[pb][0];
        float K = lg2f(p0);
        float xt = xnext;
        if (t + 1 < CRF_S) xnext = xb[(t + 1) * CRF_T + j];

        // s_j = sum_i p_i * E_ij  via packed f32x2 FMAs (4 independent chains)
        const ulonglong2* pq = reinterpret_cast<const ulonglong2*>(p_sh[pb]);
        unsigned long long a0 = 0ull, a1 = 0ull, a2 = 0ull, a3 = 0ull;
#pragma unroll
        for (int k = 0; k < CRF_T / 8; k++) {   // 8 iters, 4 f32x2 loads each
            ulonglong2 v0 = pq[2 * k];
            ulonglong2 v1 = pq[2 * k + 1];
            a0 = fma2(v0.x, E2[4 * k + 0], a0);
            a1 = fma2(v0.y, E2[4 * k + 1], a1);
            a2 = fma2(v1.x, E2[4 * k + 2], a2);
            a3 = fma2(v1.y, E2[4 * k + 3], a3);
        }
        float f0, f1, f2, f3, f4, f5, f6, f7;
        unpack2(f0, f1, a0); unpack2(f2, f3, a1);
        unpack2(f4, f5, a2); unpack2(f6, f7, a3);
        float ssum = ((f0 + f1) + (f2 + f3)) + ((f4 + f5) + (f6 + f7));

        // p'_j = ssum * 2^(L*x - K); scale bookkeeping C += K
        float pn = ssum * ex2f(fmaf(L, xt, -K));
        if (!mask_sh[t]) { pj = pn; Kacc += K; }
        p_sh[pb ^ 1][j] = pj;
        __syncthreads();
    }

    // log_norm = ( lg2( sum_j p_final_j ) + C ) / L     (natural log)
    red[j] = pj;
    __syncthreads();
    if (j == 0) {
        float sp = 0.f;
        for (int i = 0; i < CRF_T; i++) sp += red[i];
        float log_norm = (lg2f(sp) + Kacc) / L;
        red[0] = log_norm;   // reuse as broadcast slot
    }
    __syncthreads();
    float log_norm = red[0];
    __syncthreads();

    // sum unary+binary across threads, write per-batch partial
    red[j] = ub;
    __syncthreads();
    if (j == 0) {
        float su = 0.f;
        for (int i = 0; i < CRF_T; i++) su += red[i];
        g_partial[b] = -(su - log_norm);
        __threadfence();
        unsigned int v = atomicAdd(&g_count, 1u);
        is_last = (v == CRF_B - 1);
    }
    __syncthreads();

    // Last CTA: deterministic final reduction + transitions passthrough
    if (is_last) {
        __threadfence();
        float s = 0.f;
        for (int i = j; i < CRF_B; i += CRF_T) s += g_partial[i];  // fixed order
        red[j] = s;
        __syncthreads();
        if (j == 0) {
            float tot = 0.f;
            for (int i = 0; i < CRF_T; i++) tot += red[i];
            out[0] = tot / (float)CRF_B;
            g_count = 0;   // reset for next graph replay
        }
        for (int i = j; i < CRF_T * CRF_T && (1 + i) < out_size; i += CRF_T)
            out[1 + i] = trans[i];
    }
}

extern "C" void kernel_launch(void* const* d_in, const int* in_sizes, int n_in,
                              void* d_out, int out_size)
{
    const float* inputs = (const float*)d_in[0];
    const float* trans  = (const float*)d_in[1];
    const unsigned char* masks = (const unsigned char*)d_in[2];
    const int* tags = (const int*)d_in[3];
    float* out = (float*)d_out;

    crf_scan_kernel<<<CRF_B, CRF_T>>>(inputs, trans, masks, tags, out, out_size);
}